// round 1
// baseline (speedup 1.0000x reference)
#include <cuda_runtime.h>

// Problem constants
#define N_NODES 100000
#define D 128              // D_IN == D_OUT == 128
#define N_REL 4
#define N_EDGES 500000

// Transform table: T[n][r*128+f] = (W_r x[n])_f   -> 100000 x 512 f32 = 204.8 MB
__device__ float g_T[(size_t)N_NODES * (size_t)(N_REL * D)];

// ---------------------------------------------------------------------------
// GEMM: C[100000 x 640] = X[100000 x 128] @ B^T, B row n:
//   n < 512  : W[r= n/128][f = n%128][:]   (contiguous as W + n*128)
//   n >= 512 : W_sl[n-512][:]
// cols 0..511 -> g_T, cols 512..639 -> out (+ b_sl)
// Tiling: BM=128, BN=128, BK=32, 256 threads, 8x8 micro-tile per thread.
// ---------------------------------------------------------------------------
__global__ __launch_bounds__(256) void gemm_kernel(
    const float* __restrict__ X,     // [100000,128]
    const float* __restrict__ W,     // [4,128,128] == rows 0..511 of B
    const float* __restrict__ Wsl,   // [128,128]   == rows 512..639 of B
    const float* __restrict__ bsl,   // [128]
    float* __restrict__ out)         // [100000,128]
{
    constexpr int BM = 128, BN = 128, BK = 32;
    constexpr int PAD = 4; // keeps 16B alignment for float4 LDS (132*4 % 16 == 0)
    __shared__ float As[BK][BM + PAD]; // As[k][m]
    __shared__ float Bs[BK][BN + PAD]; // Bs[k][n]

    const int mt = blockIdx.x;   // 0..781
    const int nt = blockIdx.y;   // 0..4  (0..3 = relations, 4 = self-loop)
    const int m0 = mt * BM;
    const int tid = threadIdx.x;

    const float* Bsrc = (nt < N_REL) ? (W + (size_t)nt * 128 * 128) : Wsl;

    float acc[8][8];
#pragma unroll
    for (int i = 0; i < 8; i++)
#pragma unroll
        for (int j = 0; j < 8; j++) acc[i][j] = 0.0f;

    const int tx = tid & 15;     // 16 cols of threads
    const int ty = tid >> 4;     // 16 rows of threads

    for (int kt = 0; kt < D; kt += BK) {
        // load A tile: 128 rows x 32 k  (1024 float4, 4 per thread)
#pragma unroll
        for (int it = 0; it < 4; it++) {
            int i = tid + it * 256;        // 0..1023
            int m = i >> 3;                // 0..127
            int k4 = i & 7;                // 0..7 (float4 index within BK)
            int gm = m0 + m;
            float4 v = make_float4(0.f, 0.f, 0.f, 0.f);
            if (gm < N_NODES)
                v = reinterpret_cast<const float4*>(X + (size_t)gm * D + kt)[k4];
            As[k4 * 4 + 0][m] = v.x;
            As[k4 * 4 + 1][m] = v.y;
            As[k4 * 4 + 2][m] = v.z;
            As[k4 * 4 + 3][m] = v.w;
        }
        // load B tile: 128 rows(n) x 32 k
#pragma unroll
        for (int it = 0; it < 4; it++) {
            int i = tid + it * 256;
            int n = i >> 3;
            int k4 = i & 7;
            float4 v = reinterpret_cast<const float4*>(Bsrc + (size_t)n * D + kt)[k4];
            Bs[k4 * 4 + 0][n] = v.x;
            Bs[k4 * 4 + 1][n] = v.y;
            Bs[k4 * 4 + 2][n] = v.z;
            Bs[k4 * 4 + 3][n] = v.w;
        }
        __syncthreads();

#pragma unroll 8
        for (int k = 0; k < BK; k++) {
            float a[8], b[8];
            *reinterpret_cast<float4*>(&a[0]) =
                *reinterpret_cast<const float4*>(&As[k][ty * 8 + 0]);
            *reinterpret_cast<float4*>(&a[4]) =
                *reinterpret_cast<const float4*>(&As[k][ty * 8 + 4]);
            *reinterpret_cast<float4*>(&b[0]) =
                *reinterpret_cast<const float4*>(&Bs[k][tx * 8 + 0]);
            *reinterpret_cast<float4*>(&b[4]) =
                *reinterpret_cast<const float4*>(&Bs[k][tx * 8 + 4]);
#pragma unroll
            for (int i = 0; i < 8; i++)
#pragma unroll
                for (int j = 0; j < 8; j++)
                    acc[i][j] = fmaf(a[i], b[j], acc[i][j]);
        }
        __syncthreads();
    }

    // epilogue
    const int nbase = tx * 8; // column within this 128-wide N tile
    if (nt < N_REL) {
#pragma unroll
        for (int i = 0; i < 8; i++) {
            int gm = m0 + ty * 8 + i;
            if (gm >= N_NODES) break;
            float* dst = &g_T[(size_t)gm * (N_REL * D) + nt * D + nbase];
            float4 v0 = make_float4(acc[i][0], acc[i][1], acc[i][2], acc[i][3]);
            float4 v1 = make_float4(acc[i][4], acc[i][5], acc[i][6], acc[i][7]);
            reinterpret_cast<float4*>(dst)[0] = v0;
            reinterpret_cast<float4*>(dst)[1] = v1;
        }
    } else {
        float bb[8];
#pragma unroll
        for (int j = 0; j < 8; j++) bb[j] = bsl[nbase + j];
#pragma unroll
        for (int i = 0; i < 8; i++) {
            int gm = m0 + ty * 8 + i;
            if (gm >= N_NODES) break;
            float* dst = out + (size_t)gm * D + nbase;
            float4 v0 = make_float4(acc[i][0] + bb[0], acc[i][1] + bb[1],
                                    acc[i][2] + bb[2], acc[i][3] + bb[3]);
            float4 v1 = make_float4(acc[i][4] + bb[4], acc[i][5] + bb[5],
                                    acc[i][6] + bb[6], acc[i][7] + bb[7]);
            reinterpret_cast<float4*>(dst)[0] = v0;
            reinterpret_cast<float4*>(dst)[1] = v1;
        }
    }
}

// ---------------------------------------------------------------------------
// Scatter: one warp per edge. Lanes each handle one float4 (128 floats/row).
// out[tgt] += T[src, rel] + b[rel]   via red.global.add.v4.f32
// ---------------------------------------------------------------------------
__global__ __launch_bounds__(256) void scatter_kernel(
    const int* __restrict__ EI,     // [4,2,500000]
    const float* __restrict__ b,    // [4,128]
    float* __restrict__ out)        // [100000,128]
{
    const long long g = (long long)blockIdx.x * blockDim.x + threadIdx.x;
    const long long warp = g >> 5;
    const int lane = (int)(g & 31);
    if (warp >= (long long)N_REL * N_EDGES) return;

    const int r = (int)(warp / N_EDGES);
    const int e = (int)(warp - (long long)r * N_EDGES);

    const int* base = EI + (size_t)r * 2 * N_EDGES;
    const int src = base[e];             // warp-uniform broadcast load
    const int tgt = base[N_EDGES + e];

    const float4* trow =
        reinterpret_cast<const float4*>(g_T + (size_t)src * (N_REL * D) + (size_t)r * D);
    const float4* brow = reinterpret_cast<const float4*>(b + (size_t)r * D);

    float4 v = trow[lane];
    float4 bb = brow[lane];   // L1/L2-hot, 4 distinct rows total
    v.x += bb.x; v.y += bb.y; v.z += bb.z; v.w += bb.w;

    float* dst = out + (size_t)tgt * D + lane * 4;
    asm volatile("red.global.add.v4.f32 [%0], {%1, %2, %3, %4};"
                 :: "l"(dst), "f"(v.x), "f"(v.y), "f"(v.z), "f"(v.w)
                 : "memory");
}

// ---------------------------------------------------------------------------
extern "C" void kernel_launch(void* const* d_in, const int* in_sizes, int n_in,
                              void* d_out, int out_size)
{
    const float* x   = (const float*)d_in[0];   // [100000,128]
    const int*   ei  = (const int*)  d_in[1];   // [4,2,500000]
    const float* W   = (const float*)d_in[2];   // [4,128,128]
    const float* b   = (const float*)d_in[3];   // [4,128]
    const float* Wsl = (const float*)d_in[4];   // [128,128]
    const float* bsl = (const float*)d_in[5];   // [128]
    float* out = (float*)d_out;                 // [100000,128]

    // 1) Transform all nodes + self-loop (also fully initializes out)
    dim3 grid((N_NODES + 127) / 128, N_REL + 1);
    gemm_kernel<<<grid, 256>>>(x, W, Wsl, bsl, out);

    // 2) Gather + atomic scatter of precomputed messages
    const long long nwarps = (long long)N_REL * N_EDGES;     // 2,000,000
    const long long nthreads = nwarps * 32;                  // 64,000,000
    const int tpb = 256;
    const int nblocks = (int)((nthreads + tpb - 1) / tpb);   // 250,000
    scatter_kernel<<<nblocks, tpb>>>(ei, b, out);
}

// round 3
// speedup vs baseline: 1.4009x; 1.4009x over previous
#include <cuda_runtime.h>
#include <cuda_bf16.h>
#include <cstdint>

// Problem constants
#define N_NODES 100000
#define N_PAD   100096          // 782 * 128
#define D 128
#define N_REL 4
#define N_EDGES 500000

// Device scratch (globals: no allocation allowed; zero-initialized at load)
__device__ float g_T[(size_t)N_NODES * 512];                 // per-node transformed rows [r*128+f]
__device__ __nv_bfloat16 g_Xs[(size_t)N_PAD * 256];          // [xh(128) | xl(128)] per node
__device__ __nv_bfloat16 g_Bs[(size_t)640 * 256];            // rows 0..511 W, 512..639 Wsl; [Wh|Wl]

// ---------------------------------------------------------------------------
// helpers
// ---------------------------------------------------------------------------
__device__ __forceinline__ uint32_t smem_u32(const void* p) {
    uint32_t a;
    asm("{ .reg .u64 t; cvta.to.shared.u64 t, %1; cvt.u32.u64 %0, t; }" : "=r"(a) : "l"(p));
    return a;
}
__device__ __forceinline__ void ldsm_x4(uint32_t addr, uint32_t& r0, uint32_t& r1,
                                        uint32_t& r2, uint32_t& r3) {
    asm volatile("ldmatrix.sync.aligned.m8n8.x4.shared.b16 {%0,%1,%2,%3}, [%4];"
                 : "=r"(r0), "=r"(r1), "=r"(r2), "=r"(r3) : "r"(addr));
}
__device__ __forceinline__ void mma16816(float* c, uint32_t a0, uint32_t a1, uint32_t a2,
                                         uint32_t a3, uint32_t b0, uint32_t b1) {
    asm volatile("mma.sync.aligned.m16n8k16.row.col.f32.bf16.bf16.f32 "
                 "{%0,%1,%2,%3}, {%4,%5,%6,%7}, {%8,%9}, {%0,%1,%2,%3};"
                 : "+f"(c[0]), "+f"(c[1]), "+f"(c[2]), "+f"(c[3])
                 : "r"(a0), "r"(a1), "r"(a2), "r"(a3), "r"(b0), "r"(b1));
}

// ---------------------------------------------------------------------------
// Conversion kernels: fp32 -> (bf16 hi, bf16 lo) split
// ---------------------------------------------------------------------------
__global__ __launch_bounds__(256) void conv_x_kernel(const float* __restrict__ x) {
    size_t i = (size_t)blockIdx.x * blockDim.x + threadIdx.x;  // one float4 per thread
    if (i >= (size_t)N_NODES * 32) return;
    size_t row = i >> 5;
    int c4 = (int)(i & 31);
    float4 v = reinterpret_cast<const float4*>(x)[i];
    __nv_bfloat16 h[4], l[4];
    float f[4] = {v.x, v.y, v.z, v.w};
#pragma unroll
    for (int j = 0; j < 4; j++) {
        h[j] = __float2bfloat16(f[j]);
        l[j] = __float2bfloat16(f[j] - __bfloat162float(h[j]));
    }
    *reinterpret_cast<uint2*>(&g_Xs[row * 256 + c4 * 4])       = *reinterpret_cast<uint2*>(h);
    *reinterpret_cast<uint2*>(&g_Xs[row * 256 + 128 + c4 * 4]) = *reinterpret_cast<uint2*>(l);
}

__global__ __launch_bounds__(256) void conv_w_kernel(const float* __restrict__ W,
                                                     const float* __restrict__ Wsl) {
    int i = blockIdx.x * blockDim.x + threadIdx.x;  // one float4 per thread, 640*32 total
    if (i >= 640 * 32) return;
    int row = i >> 5;
    int c4 = i & 31;
    const float* src = (row < 512) ? (W + (size_t)row * 128) : (Wsl + (size_t)(row - 512) * 128);
    float4 v = reinterpret_cast<const float4*>(src)[c4];
    __nv_bfloat16 h[4], l[4];
    float f[4] = {v.x, v.y, v.z, v.w};
#pragma unroll
    for (int j = 0; j < 4; j++) {
        h[j] = __float2bfloat16(f[j]);
        l[j] = __float2bfloat16(f[j] - __bfloat162float(h[j]));
    }
    *reinterpret_cast<uint2*>(&g_Bs[(size_t)row * 256 + c4 * 4])       = *reinterpret_cast<uint2*>(h);
    *reinterpret_cast<uint2*>(&g_Bs[(size_t)row * 256 + 128 + c4 * 4]) = *reinterpret_cast<uint2*>(l);
}

// ---------------------------------------------------------------------------
// mma.sync GEMM: C[100096 x 640] = Xsplit @ Bsplit^T (3-term bf16 split)
//   grid = (782, 5); CTA tile M=128, N=128; 8 warps as 4(M) x 2(N), warp 32x64.
//   BK=64, 6 K-steps: (acol,bcol) = (0,0)(64,64) | (128,0)(192,64) | (0,128)(64,192)
//   nt<4 -> g_T ; nt==4 -> out (+bsl)
// SMEM: 128 rows x 64 bf16 (128B/row), XOR-swizzle on 16B chunks: ch ^= (row&7)
// ---------------------------------------------------------------------------
__global__ __launch_bounds__(256, 2) void gemm_mma_kernel(const float* __restrict__ bsl,
                                                          float* __restrict__ out) {
    __shared__ __nv_bfloat16 sA[128 * 64];
    __shared__ __nv_bfloat16 sB[128 * 64];

    const int tid = threadIdx.x;
    const int lane = tid & 31;
    const int wid = tid >> 5;
    const int wm = wid & 3;      // 0..3 : M sub-tile (32 rows)
    const int wn = wid >> 2;     // 0..1 : N sub-tile (64 cols)
    const int mt = blockIdx.x;   // 0..781
    const int nt = blockIdx.y;   // 0..4
    const int m0 = mt * 128;

    float acc[2][8][4];
#pragma unroll
    for (int i = 0; i < 2; i++)
#pragma unroll
        for (int j = 0; j < 8; j++)
#pragma unroll
            for (int k = 0; k < 4; k++) acc[i][j][k] = 0.0f;

    const __nv_bfloat16* Abase = g_Xs + (size_t)m0 * 256;
    const __nv_bfloat16* Bbase = g_Bs + (size_t)nt * 128 * 256;
    const uint32_t sAu = smem_u32(sA);
    const uint32_t sBu = smem_u32(sB);

    const int acol_tab[6] = {0, 64, 128, 192, 0, 64};
    const int bcol_tab[6] = {0, 64, 0, 64, 128, 192};

#pragma unroll 1
    for (int step = 0; step < 6; step++) {
        const int ac = acol_tab[step];
        const int bc = bcol_tab[step];
        // load 128x64 tiles (1024 16B-chunks each; 4 per thread per tile)
#pragma unroll
        for (int it = 0; it < 4; it++) {
            int idx = tid + it * 256;
            int row = idx >> 3;
            int ch = idx & 7;
            int sw = (ch ^ (row & 7)) << 4;
            float4 va = *reinterpret_cast<const float4*>(Abase + (size_t)row * 256 + ac + ch * 8);
            *reinterpret_cast<float4*>(reinterpret_cast<char*>(sA) + row * 128 + sw) = va;
            float4 vb = *reinterpret_cast<const float4*>(Bbase + (size_t)row * 256 + bc + ch * 8);
            *reinterpret_cast<float4*>(reinterpret_cast<char*>(sB) + row * 128 + sw) = vb;
        }
        __syncthreads();

#pragma unroll
        for (int kq = 0; kq < 4; kq++) {  // k = kq*16 within BK=64
            uint32_t a[2][4];
#pragma unroll
            for (int mf = 0; mf < 2; mf++) {
                int row = wm * 32 + mf * 16 + (lane & 15);
                int kch = kq * 2 + (lane >> 4);
                uint32_t addr = sAu + row * 128 + ((kch ^ (row & 7)) << 4);
                ldsm_x4(addr, a[mf][0], a[mf][1], a[mf][2], a[mf][3]);
            }
            uint32_t b[8][2];
#pragma unroll
            for (int np = 0; np < 4; np++) {
                int n = wn * 64 + np * 16 + ((lane >> 4) << 3) + (lane & 7);
                int kch = kq * 2 + ((lane >> 3) & 1);
                uint32_t addr = sBu + n * 128 + ((kch ^ (n & 7)) << 4);
                ldsm_x4(addr, b[np * 2][0], b[np * 2][1], b[np * 2 + 1][0], b[np * 2 + 1][1]);
            }
#pragma unroll
            for (int mf = 0; mf < 2; mf++)
#pragma unroll
                for (int nf = 0; nf < 8; nf++)
                    mma16816(acc[mf][nf], a[mf][0], a[mf][1], a[mf][2], a[mf][3],
                             b[nf][0], b[nf][1]);
        }
        __syncthreads();
    }

    // Epilogue. D frag: c0,c1 -> row lane/4, cols 2*(lane%4)+{0,1}; c2,c3 -> row+8.
    const int r0 = lane >> 2;
    const int c0 = (lane & 3) * 2;
    if (nt < N_REL) {
#pragma unroll
        for (int mf = 0; mf < 2; mf++) {
#pragma unroll
            for (int half = 0; half < 2; half++) {
                int gm = m0 + wm * 32 + mf * 16 + r0 + half * 8;
                if (gm >= N_NODES) continue;
                float* dst = g_T + (size_t)gm * 512 + nt * 128 + wn * 64 + c0;
#pragma unroll
                for (int nf = 0; nf < 8; nf++) {
                    float2 v = make_float2(acc[mf][nf][half * 2], acc[mf][nf][half * 2 + 1]);
                    *reinterpret_cast<float2*>(dst + nf * 8) = v;
                }
            }
        }
    } else {
#pragma unroll
        for (int mf = 0; mf < 2; mf++) {
#pragma unroll
            for (int half = 0; half < 2; half++) {
                int gm = m0 + wm * 32 + mf * 16 + r0 + half * 8;
                if (gm >= N_NODES) continue;
                float* dst = out + (size_t)gm * 128 + wn * 64 + c0;
#pragma unroll
                for (int nf = 0; nf < 8; nf++) {
                    float2 bb = *reinterpret_cast<const float2*>(bsl + wn * 64 + c0 + nf * 8);
                    float2 v = make_float2(acc[mf][nf][half * 2] + bb.x,
                                           acc[mf][nf][half * 2 + 1] + bb.y);
                    *reinterpret_cast<float2*>(dst + nf * 8) = v;
                }
            }
        }
    }
}

// ---------------------------------------------------------------------------
// Scatter: one warp per edge; out[tgt] += T[src, rel] + b[rel]
// ---------------------------------------------------------------------------
__global__ __launch_bounds__(256) void scatter_kernel(
    const int* __restrict__ EI, const float* __restrict__ b, float* __restrict__ out) {
    const long long g = (long long)blockIdx.x * blockDim.x + threadIdx.x;
    const long long warp = g >> 5;
    const int lane = (int)(g & 31);
    if (warp >= (long long)N_REL * N_EDGES) return;

    const int r = (int)(warp / N_EDGES);
    const int e = (int)(warp - (long long)r * N_EDGES);

    const int* base = EI + (size_t)r * 2 * N_EDGES;
    const int src = base[e];
    const int tgt = base[N_EDGES + e];

    const float4* trow = reinterpret_cast<const float4*>(g_T + (size_t)src * 512 + (size_t)r * 128);
    const float4* brow = reinterpret_cast<const float4*>(b + (size_t)r * 128);

    float4 v = trow[lane];
    float4 bb = brow[lane];
    v.x += bb.x; v.y += bb.y; v.z += bb.z; v.w += bb.w;

    float* dst = out + (size_t)tgt * 128 + lane * 4;
    asm volatile("red.global.add.v4.f32 [%0], {%1, %2, %3, %4};"
                 :: "l"(dst), "f"(v.x), "f"(v.y), "f"(v.z), "f"(v.w) : "memory");
}

// ---------------------------------------------------------------------------
extern "C" void kernel_launch(void* const* d_in, const int* in_sizes, int n_in,
                              void* d_out, int out_size) {
    const float* x   = (const float*)d_in[0];   // [100000,128]
    const int*   ei  = (const int*)  d_in[1];   // [4,2,500000]
    const float* W   = (const float*)d_in[2];   // [4,128,128]
    const float* b   = (const float*)d_in[3];   // [4,128]
    const float* Wsl = (const float*)d_in[4];   // [128,128]
    const float* bsl = (const float*)d_in[5];   // [128]
    float* out = (float*)d_out;                 // [100000,128]

    // 1) bf16 hi/lo split conversion
    conv_x_kernel<<<(N_NODES * 32 + 255) / 256, 256>>>(x);
    conv_w_kernel<<<(640 * 32 + 255) / 256, 256>>>(W, Wsl);

    // 2) tensor-core (mma.sync) transform of all nodes (also initializes out via nt==4)
    dim3 grid(782, 5);
    gemm_mma_kernel<<<grid, 256>>>(bsl, out);

    // 3) gather + atomic scatter of precomputed messages
    const long long nthreads = (long long)N_REL * N_EDGES * 32;
    scatter_kernel<<<(int)((nthreads + 255) / 256), 256>>>(ei, b, out);
}

// round 4
// speedup vs baseline: 1.6646x; 1.1883x over previous
#include <cuda_runtime.h>
#include <cuda_bf16.h>
#include <cstdint>

// Problem constants
#define N_NODES 100000
#define N_PAD   100096          // 782 * 128
#define NT      100096          // padded bin count for sort
#define NBLK1K  98              // ceil(NT/1024)
#define D 128
#define N_REL 4
#define N_EDGES 500000
#define TOT_E   (N_REL * N_EDGES)   // 2,000,000

// Device scratch (globals; zero-initialized at module load)
__device__ float g_T[(size_t)N_NODES * 512];                 // per-node transformed rows
__device__ __nv_bfloat16 g_Xs[(size_t)N_PAD * 256];          // [xh(128)|xl(128)] per node
__device__ __nv_bfloat16 g_Bs[(size_t)640 * 256];            // W rows 0..511, Wsl 512..639; [Wh|Wl]
__device__ int g_cnt[NT];
__device__ int g_off[NT + 1];
__device__ int g_cursor[NT];
__device__ int g_part[NBLK1K];
__device__ int g_partoff[NBLK1K];
__device__ int g_payload[TOT_E];

// ---------------------------------------------------------------------------
// helpers
// ---------------------------------------------------------------------------
__device__ __forceinline__ uint32_t smem_u32(const void* p) {
    uint32_t a;
    asm("{ .reg .u64 t; cvta.to.shared.u64 t, %1; cvt.u32.u64 %0, t; }" : "=r"(a) : "l"(p));
    return a;
}
__device__ __forceinline__ void ldsm_x4(uint32_t addr, uint32_t& r0, uint32_t& r1,
                                        uint32_t& r2, uint32_t& r3) {
    asm volatile("ldmatrix.sync.aligned.m8n8.x4.shared.b16 {%0,%1,%2,%3}, [%4];"
                 : "=r"(r0), "=r"(r1), "=r"(r2), "=r"(r3) : "r"(addr));
}
__device__ __forceinline__ void mma16816(float* c, uint32_t a0, uint32_t a1, uint32_t a2,
                                         uint32_t a3, uint32_t b0, uint32_t b1) {
    asm volatile("mma.sync.aligned.m16n8k16.row.col.f32.bf16.bf16.f32 "
                 "{%0,%1,%2,%3}, {%4,%5,%6,%7}, {%8,%9}, {%0,%1,%2,%3};"
                 : "+f"(c[0]), "+f"(c[1]), "+f"(c[2]), "+f"(c[3])
                 : "r"(a0), "r"(a1), "r"(a2), "r"(a3), "r"(b0), "r"(b1));
}

// ---------------------------------------------------------------------------
// Conversion kernels: fp32 -> (bf16 hi, bf16 lo) split
// ---------------------------------------------------------------------------
__global__ __launch_bounds__(256) void conv_x_kernel(const float* __restrict__ x) {
    size_t i = (size_t)blockIdx.x * blockDim.x + threadIdx.x;
    if (i >= (size_t)N_NODES * 32) return;
    size_t row = i >> 5;
    int c4 = (int)(i & 31);
    float4 v = reinterpret_cast<const float4*>(x)[i];
    __nv_bfloat16 h[4], l[4];
    float f[4] = {v.x, v.y, v.z, v.w};
#pragma unroll
    for (int j = 0; j < 4; j++) {
        h[j] = __float2bfloat16(f[j]);
        l[j] = __float2bfloat16(f[j] - __bfloat162float(h[j]));
    }
    *reinterpret_cast<uint2*>(&g_Xs[row * 256 + c4 * 4])       = *reinterpret_cast<uint2*>(h);
    *reinterpret_cast<uint2*>(&g_Xs[row * 256 + 128 + c4 * 4]) = *reinterpret_cast<uint2*>(l);
}

__global__ __launch_bounds__(256) void conv_w_kernel(const float* __restrict__ W,
                                                     const float* __restrict__ Wsl) {
    int i = blockIdx.x * blockDim.x + threadIdx.x;
    if (i >= 640 * 32) return;
    int row = i >> 5;
    int c4 = i & 31;
    const float* src = (row < 512) ? (W + (size_t)row * 128) : (Wsl + (size_t)(row - 512) * 128);
    float4 v = reinterpret_cast<const float4*>(src)[c4];
    __nv_bfloat16 h[4], l[4];
    float f[4] = {v.x, v.y, v.z, v.w};
#pragma unroll
    for (int j = 0; j < 4; j++) {
        h[j] = __float2bfloat16(f[j]);
        l[j] = __float2bfloat16(f[j] - __bfloat162float(h[j]));
    }
    *reinterpret_cast<uint2*>(&g_Bs[(size_t)row * 256 + c4 * 4])       = *reinterpret_cast<uint2*>(h);
    *reinterpret_cast<uint2*>(&g_Bs[(size_t)row * 256 + 128 + c4 * 4]) = *reinterpret_cast<uint2*>(l);
}

// ---------------------------------------------------------------------------
// mma.sync GEMM (unchanged, proven): C[100096 x 640] = Xsplit @ Bsplit^T
// ---------------------------------------------------------------------------
__global__ __launch_bounds__(256, 2) void gemm_mma_kernel(const float* __restrict__ bsl,
                                                          float* __restrict__ out) {
    __shared__ __nv_bfloat16 sA[128 * 64];
    __shared__ __nv_bfloat16 sB[128 * 64];

    const int tid = threadIdx.x;
    const int lane = tid & 31;
    const int wid = tid >> 5;
    const int wm = wid & 3;
    const int wn = wid >> 2;
    const int mt = blockIdx.x;
    const int nt = blockIdx.y;
    const int m0 = mt * 128;

    float acc[2][8][4];
#pragma unroll
    for (int i = 0; i < 2; i++)
#pragma unroll
        for (int j = 0; j < 8; j++)
#pragma unroll
            for (int k = 0; k < 4; k++) acc[i][j][k] = 0.0f;

    const __nv_bfloat16* Abase = g_Xs + (size_t)m0 * 256;
    const __nv_bfloat16* Bbase = g_Bs + (size_t)nt * 128 * 256;
    const uint32_t sAu = smem_u32(sA);
    const uint32_t sBu = smem_u32(sB);

    const int acol_tab[6] = {0, 64, 128, 192, 0, 64};
    const int bcol_tab[6] = {0, 64, 0, 64, 128, 192};

#pragma unroll 1
    for (int step = 0; step < 6; step++) {
        const int ac = acol_tab[step];
        const int bc = bcol_tab[step];
#pragma unroll
        for (int it = 0; it < 4; it++) {
            int idx = tid + it * 256;
            int row = idx >> 3;
            int ch = idx & 7;
            int sw = (ch ^ (row & 7)) << 4;
            float4 va = *reinterpret_cast<const float4*>(Abase + (size_t)row * 256 + ac + ch * 8);
            *reinterpret_cast<float4*>(reinterpret_cast<char*>(sA) + row * 128 + sw) = va;
            float4 vb = *reinterpret_cast<const float4*>(Bbase + (size_t)row * 256 + bc + ch * 8);
            *reinterpret_cast<float4*>(reinterpret_cast<char*>(sB) + row * 128 + sw) = vb;
        }
        __syncthreads();

#pragma unroll
        for (int kq = 0; kq < 4; kq++) {
            uint32_t a[2][4];
#pragma unroll
            for (int mf = 0; mf < 2; mf++) {
                int row = wm * 32 + mf * 16 + (lane & 15);
                int kch = kq * 2 + (lane >> 4);
                uint32_t addr = sAu + row * 128 + ((kch ^ (row & 7)) << 4);
                ldsm_x4(addr, a[mf][0], a[mf][1], a[mf][2], a[mf][3]);
            }
            uint32_t b[8][2];
#pragma unroll
            for (int np = 0; np < 4; np++) {
                int n = wn * 64 + np * 16 + ((lane >> 4) << 3) + (lane & 7);
                int kch = kq * 2 + ((lane >> 3) & 1);
                uint32_t addr = sBu + n * 128 + ((kch ^ (n & 7)) << 4);
                ldsm_x4(addr, b[np * 2][0], b[np * 2][1], b[np * 2 + 1][0], b[np * 2 + 1][1]);
            }
#pragma unroll
            for (int mf = 0; mf < 2; mf++)
#pragma unroll
                for (int nf = 0; nf < 8; nf++)
                    mma16816(acc[mf][nf], a[mf][0], a[mf][1], a[mf][2], a[mf][3],
                             b[nf][0], b[nf][1]);
        }
        __syncthreads();
    }

    const int r0 = lane >> 2;
    const int c0 = (lane & 3) * 2;
    if (nt < N_REL) {
#pragma unroll
        for (int mf = 0; mf < 2; mf++) {
#pragma unroll
            for (int half = 0; half < 2; half++) {
                int gm = m0 + wm * 32 + mf * 16 + r0 + half * 8;
                if (gm >= N_NODES) continue;
                float* dst = g_T + (size_t)gm * 512 + nt * 128 + wn * 64 + c0;
#pragma unroll
                for (int nf = 0; nf < 8; nf++) {
                    float2 v = make_float2(acc[mf][nf][half * 2], acc[mf][nf][half * 2 + 1]);
                    *reinterpret_cast<float2*>(dst + nf * 8) = v;
                }
            }
        }
    } else {
#pragma unroll
        for (int mf = 0; mf < 2; mf++) {
#pragma unroll
            for (int half = 0; half < 2; half++) {
                int gm = m0 + wm * 32 + mf * 16 + r0 + half * 8;
                if (gm >= N_NODES) continue;
                float* dst = out + (size_t)gm * 128 + wn * 64 + c0;
#pragma unroll
                for (int nf = 0; nf < 8; nf++) {
                    float2 bb = *reinterpret_cast<const float2*>(bsl + wn * 64 + c0 + nf * 8);
                    float2 v = make_float2(acc[mf][nf][half * 2] + bb.x,
                                           acc[mf][nf][half * 2 + 1] + bb.y);
                    *reinterpret_cast<float2*>(dst + nf * 8) = v;
                }
            }
        }
    }
}

// ---------------------------------------------------------------------------
// Counting sort by target
// ---------------------------------------------------------------------------
__global__ __launch_bounds__(256) void zero_cnt_kernel() {
    int i = blockIdx.x * blockDim.x + threadIdx.x;
    if (i < NT) g_cnt[i] = 0;
}

__global__ __launch_bounds__(256) void hist_kernel(const int* __restrict__ EI) {
    int i = blockIdx.x * blockDim.x + threadIdx.x;
    if (i >= TOT_E) return;
    int r = i / N_EDGES;
    int e = i - r * N_EDGES;
    int tgt = EI[(size_t)r * 2 * N_EDGES + N_EDGES + e];
    atomicAdd(&g_cnt[tgt], 1);
}

// per-1024 block sums
__global__ __launch_bounds__(256) void scan_part_kernel() {
    __shared__ int s[256];
    int b = blockIdx.x, t = threadIdx.x;
    int base = b * 1024 + t * 4;
    int v = 0;
#pragma unroll
    for (int j = 0; j < 4; j++) {
        int idx = base + j;
        if (idx < NT) v += g_cnt[idx];
    }
    s[t] = v;
    __syncthreads();
    for (int off = 128; off > 0; off >>= 1) {
        if (t < off) s[t] += s[t + off];
        __syncthreads();
    }
    if (t == 0) g_part[b] = s[0];
}

// scan of 98 partials (one block of 128)
__global__ __launch_bounds__(128) void scan_top_kernel() {
    __shared__ int s[128];
    int t = threadIdx.x;
    int v = (t < NBLK1K) ? g_part[t] : 0;
    s[t] = v;
    __syncthreads();
    for (int d = 1; d < 128; d <<= 1) {
        int add = (t >= d) ? s[t - d] : 0;
        __syncthreads();
        s[t] += add;
        __syncthreads();
    }
    if (t < NBLK1K) g_partoff[t] = s[t] - v;
    if (t == NBLK1K - 1) g_off[NT] = s[t];
}

// final per-element exclusive offsets (+ cursor copy)
__global__ __launch_bounds__(256) void scan_final_kernel() {
    __shared__ int s[256];
    int b = blockIdx.x, t = threadIdx.x;
    int base = b * 1024 + t * 4;
    int e[4], local[4];
    int sum = 0;
#pragma unroll
    for (int j = 0; j < 4; j++) {
        int idx = base + j;
        e[j] = (idx < NT) ? g_cnt[idx] : 0;
        local[j] = sum;
        sum += e[j];
    }
    s[t] = sum;
    __syncthreads();
    int own = sum;
    for (int d = 1; d < 256; d <<= 1) {
        int add = (t >= d) ? s[t - d] : 0;
        __syncthreads();
        s[t] += add;
        __syncthreads();
    }
    int texcl = s[t] - own;
    int baseoff = g_partoff[b] + texcl;
#pragma unroll
    for (int j = 0; j < 4; j++) {
        int idx = base + j;
        if (idx < NT) {
            int o = baseoff + local[j];
            g_off[idx] = o;
            g_cursor[idx] = o;
        }
    }
}

__global__ __launch_bounds__(256) void reorder_kernel(const int* __restrict__ EI) {
    int i = blockIdx.x * blockDim.x + threadIdx.x;
    if (i >= TOT_E) return;
    int r = i / N_EDGES;
    int e = i - r * N_EDGES;
    const int* base = EI + (size_t)r * 2 * N_EDGES;
    int src = base[e];
    int tgt = base[N_EDGES + e];
    int pos = atomicAdd(&g_cursor[tgt], 1);
    g_payload[pos] = (r << 17) | src;
}

// ---------------------------------------------------------------------------
// Gather: one warp per target; out[t] += sum_e T[src_e, r_e] + cnt_r * b_r
// (warp exclusively owns row t -> plain RMW, no atomics)
// ---------------------------------------------------------------------------
__global__ __launch_bounds__(256) void gather_kernel(const float* __restrict__ b,
                                                     float* __restrict__ out) {
    const int lane = threadIdx.x & 31;
    const int wid = threadIdx.x >> 5;
    const int t = blockIdx.x * 8 + wid;
    if (t >= N_NODES) return;

    const int beg = g_off[t];
    const int end = g_off[t + 1];
    if (beg == end) return;

    float4 acc = make_float4(0.f, 0.f, 0.f, 0.f);
    int c0 = 0, c1 = 0, c2 = 0, c3 = 0;

    for (int base = beg; base < end; base += 32) {
        int i = base + lane;
        int p = (i < end) ? g_payload[i] : 0;
        int m = min(end - base, 32);
        for (int j = 0; j < m; j++) {
            int pj = __shfl_sync(0xffffffffu, p, j);
            int r = pj >> 17;
            int src = pj & 131071;
            float4 v = reinterpret_cast<const float4*>(
                g_T + (size_t)src * 512 + (size_t)r * 128)[lane];
            acc.x += v.x; acc.y += v.y; acc.z += v.z; acc.w += v.w;
            c0 += (r == 0); c1 += (r == 1); c2 += (r == 2); c3 += (r == 3);
        }
    }

    float cf[4] = {(float)c0, (float)c1, (float)c2, (float)c3};
#pragma unroll
    for (int r = 0; r < 4; r++) {
        float4 br = reinterpret_cast<const float4*>(b + (size_t)r * 128)[lane];
        acc.x += cf[r] * br.x; acc.y += cf[r] * br.y;
        acc.z += cf[r] * br.z; acc.w += cf[r] * br.w;
    }

    float4* orow = reinterpret_cast<float4*>(out + (size_t)t * 128);
    float4 o = orow[lane];   // self-loop result from GEMM
    o.x += acc.x; o.y += acc.y; o.z += acc.z; o.w += acc.w;
    orow[lane] = o;
}

// ---------------------------------------------------------------------------
extern "C" void kernel_launch(void* const* d_in, const int* in_sizes, int n_in,
                              void* d_out, int out_size) {
    const float* x   = (const float*)d_in[0];   // [100000,128]
    const int*   ei  = (const int*)  d_in[1];   // [4,2,500000]
    const float* W   = (const float*)d_in[2];   // [4,128,128]
    const float* b   = (const float*)d_in[3];   // [4,128]
    const float* Wsl = (const float*)d_in[4];   // [128,128]
    const float* bsl = (const float*)d_in[5];   // [128]
    float* out = (float*)d_out;                 // [100000,128]

    // A) bf16 hi/lo split conversion + tensor-core transform (writes g_T and out selfloop)
    conv_x_kernel<<<(N_NODES * 32 + 255) / 256, 256>>>(x);
    conv_w_kernel<<<(640 * 32 + 255) / 256, 256>>>(W, Wsl);
    dim3 grid(782, 5);
    gemm_mma_kernel<<<grid, 256>>>(bsl, out);

    // B) counting sort of edges by target
    zero_cnt_kernel<<<(NT + 255) / 256, 256>>>();
    hist_kernel<<<(TOT_E + 255) / 256, 256>>>(ei);
    scan_part_kernel<<<NBLK1K, 256>>>();
    scan_top_kernel<<<1, 128>>>();
    scan_final_kernel<<<NBLK1K, 256>>>();
    reorder_kernel<<<(TOT_E + 255) / 256, 256>>>(ei);

    // C) atomic-free per-target gather + bias + self-loop RMW
    gather_kernel<<<(N_NODES + 7) / 8, 256>>>(b, out);
}

// round 5
// speedup vs baseline: 1.9183x; 1.1524x over previous
#include <cuda_runtime.h>
#include <cuda_fp16.h>
#include <cstdint>

// Problem constants
#define N_NODES 100000
#define N_PAD   100096          // 782 * 128
#define NT      100096          // padded bin count for sort
#define NBLK1K  98              // ceil(NT/1024)
#define D 128
#define N_REL 4
#define N_EDGES 500000
#define TOT_E   (N_REL * N_EDGES)   // 2,000,000

// Device scratch (globals; no runtime allocation allowed)
__device__ float g_T[(size_t)N_NODES * 512];        // per-node transformed rows
__device__ __half g_Xs[(size_t)N_PAD * 256];        // [xh(128)|xl(128)] per node (fp16)
__device__ __half g_Bs[(size_t)640 * 128];          // Wh rows: 0..511 W, 512..639 Wsl (fp16 hi)
__device__ int g_cnt[NT];
__device__ int g_off[NT + 1];
__device__ int g_cursor[NT];
__device__ int g_part[NBLK1K];
__device__ int g_partoff[NBLK1K];
__device__ int g_payload[TOT_E];

// ---------------------------------------------------------------------------
// helpers
// ---------------------------------------------------------------------------
__device__ __forceinline__ uint32_t smem_u32(const void* p) {
    uint32_t a;
    asm("{ .reg .u64 t; cvta.to.shared.u64 t, %1; cvt.u32.u64 %0, t; }" : "=r"(a) : "l"(p));
    return a;
}
__device__ __forceinline__ void ldsm_x4(uint32_t addr, uint32_t& r0, uint32_t& r1,
                                        uint32_t& r2, uint32_t& r3) {
    asm volatile("ldmatrix.sync.aligned.m8n8.x4.shared.b16 {%0,%1,%2,%3}, [%4];"
                 : "=r"(r0), "=r"(r1), "=r"(r2), "=r"(r3) : "r"(addr));
}
__device__ __forceinline__ void mma16816(float* c, uint32_t a0, uint32_t a1, uint32_t a2,
                                         uint32_t a3, uint32_t b0, uint32_t b1) {
    asm volatile("mma.sync.aligned.m16n8k16.row.col.f32.f16.f16.f32 "
                 "{%0,%1,%2,%3}, {%4,%5,%6,%7}, {%8,%9}, {%0,%1,%2,%3};"
                 : "+f"(c[0]), "+f"(c[1]), "+f"(c[2]), "+f"(c[3])
                 : "r"(a0), "r"(a1), "r"(a2), "r"(a3), "r"(b0), "r"(b1));
}

// ---------------------------------------------------------------------------
// Conversion kernels: fp32 -> (fp16 hi, fp16 lo) split
// ---------------------------------------------------------------------------
__global__ __launch_bounds__(256) void conv_x_kernel(const float* __restrict__ x) {
    size_t i = (size_t)blockIdx.x * blockDim.x + threadIdx.x;
    if (i >= (size_t)N_NODES * 32) return;
    size_t row = i >> 5;
    int c4 = (int)(i & 31);
    float4 v = reinterpret_cast<const float4*>(x)[i];
    __half h[4], l[4];
    float f[4] = {v.x, v.y, v.z, v.w};
#pragma unroll
    for (int j = 0; j < 4; j++) {
        h[j] = __float2half_rn(f[j]);
        l[j] = __float2half_rn(f[j] - __half2float(h[j]));
    }
    *reinterpret_cast<uint2*>(&g_Xs[row * 256 + c4 * 4])       = *reinterpret_cast<uint2*>(h);
    *reinterpret_cast<uint2*>(&g_Xs[row * 256 + 128 + c4 * 4]) = *reinterpret_cast<uint2*>(l);
}

__global__ __launch_bounds__(256) void conv_w_kernel(const float* __restrict__ W,
                                                     const float* __restrict__ Wsl) {
    int i = blockIdx.x * blockDim.x + threadIdx.x;
    if (i >= 640 * 32) return;
    int row = i >> 5;
    int c4 = i & 31;
    const float* src = (row < 512) ? (W + (size_t)row * 128) : (Wsl + (size_t)(row - 512) * 128);
    float4 v = reinterpret_cast<const float4*>(src)[c4];
    __half h[4];
    h[0] = __float2half_rn(v.x); h[1] = __float2half_rn(v.y);
    h[2] = __float2half_rn(v.z); h[3] = __float2half_rn(v.w);
    *reinterpret_cast<uint2*>(&g_Bs[(size_t)row * 128 + c4 * 4]) = *reinterpret_cast<uint2*>(h);
}

// ---------------------------------------------------------------------------
// mma.sync GEMM: C[100096 x 640] = (xh + xl) @ Wh^T   (fp16 2-term split)
//   grid = (782, 5); CTA tile M=128, N=128; 8 warps 4(M)x2(N), warp 32x64.
//   4 K-steps of 64: acol {0,64,128,192} (xh then xl), bcol {0,64,0,64} (Wh)
//   nt<4 -> g_T ; nt==4 -> out (+bsl)
// ---------------------------------------------------------------------------
__global__ __launch_bounds__(256, 2) void gemm_mma_kernel(const float* __restrict__ bsl,
                                                          float* __restrict__ out) {
    __shared__ __half sA[128 * 64];
    __shared__ __half sB[128 * 64];

    const int tid = threadIdx.x;
    const int lane = tid & 31;
    const int wid = tid >> 5;
    const int wm = wid & 3;
    const int wn = wid >> 2;
    const int mt = blockIdx.x;
    const int nt = blockIdx.y;
    const int m0 = mt * 128;

    float acc[2][8][4];
#pragma unroll
    for (int i = 0; i < 2; i++)
#pragma unroll
        for (int j = 0; j < 8; j++)
#pragma unroll
            for (int k = 0; k < 4; k++) acc[i][j][k] = 0.0f;

    const __half* Abase = g_Xs + (size_t)m0 * 256;
    const __half* Bbase = g_Bs + (size_t)nt * 128 * 128;
    const uint32_t sAu = smem_u32(sA);
    const uint32_t sBu = smem_u32(sB);

    const int acol_tab[4] = {0, 64, 128, 192};
    const int bcol_tab[4] = {0, 64, 0, 64};

#pragma unroll 1
    for (int step = 0; step < 4; step++) {
        const int ac = acol_tab[step];
        const int bc = bcol_tab[step];
#pragma unroll
        for (int it = 0; it < 4; it++) {
            int idx = tid + it * 256;
            int row = idx >> 3;
            int ch = idx & 7;
            int sw = (ch ^ (row & 7)) << 4;
            float4 va = *reinterpret_cast<const float4*>(Abase + (size_t)row * 256 + ac + ch * 8);
            *reinterpret_cast<float4*>(reinterpret_cast<char*>(sA) + row * 128 + sw) = va;
            float4 vb = *reinterpret_cast<const float4*>(Bbase + (size_t)row * 128 + bc + ch * 8);
            *reinterpret_cast<float4*>(reinterpret_cast<char*>(sB) + row * 128 + sw) = vb;
        }
        __syncthreads();

#pragma unroll
        for (int kq = 0; kq < 4; kq++) {
            uint32_t a[2][4];
#pragma unroll
            for (int mf = 0; mf < 2; mf++) {
                int row = wm * 32 + mf * 16 + (lane & 15);
                int kch = kq * 2 + (lane >> 4);
                uint32_t addr = sAu + row * 128 + ((kch ^ (row & 7)) << 4);
                ldsm_x4(addr, a[mf][0], a[mf][1], a[mf][2], a[mf][3]);
            }
            uint32_t b[8][2];
#pragma unroll
            for (int np = 0; np < 4; np++) {
                int n = wn * 64 + np * 16 + ((lane >> 4) << 3) + (lane & 7);
                int kch = kq * 2 + ((lane >> 3) & 1);
                uint32_t addr = sBu + n * 128 + ((kch ^ (n & 7)) << 4);
                ldsm_x4(addr, b[np * 2][0], b[np * 2][1], b[np * 2 + 1][0], b[np * 2 + 1][1]);
            }
#pragma unroll
            for (int mf = 0; mf < 2; mf++)
#pragma unroll
                for (int nf = 0; nf < 8; nf++)
                    mma16816(acc[mf][nf], a[mf][0], a[mf][1], a[mf][2], a[mf][3],
                             b[nf][0], b[nf][1]);
        }
        __syncthreads();
    }

    const int r0 = lane >> 2;
    const int c0 = (lane & 3) * 2;
    if (nt < N_REL) {
#pragma unroll
        for (int mf = 0; mf < 2; mf++) {
#pragma unroll
            for (int half = 0; half < 2; half++) {
                int gm = m0 + wm * 32 + mf * 16 + r0 + half * 8;
                if (gm >= N_NODES) continue;
                float* dst = g_T + (size_t)gm * 512 + nt * 128 + wn * 64 + c0;
#pragma unroll
                for (int nf = 0; nf < 8; nf++) {
                    float2 v = make_float2(acc[mf][nf][half * 2], acc[mf][nf][half * 2 + 1]);
                    *reinterpret_cast<float2*>(dst + nf * 8) = v;
                }
            }
        }
    } else {
#pragma unroll
        for (int mf = 0; mf < 2; mf++) {
#pragma unroll
            for (int half = 0; half < 2; half++) {
                int gm = m0 + wm * 32 + mf * 16 + r0 + half * 8;
                if (gm >= N_NODES) continue;
                float* dst = out + (size_t)gm * 128 + wn * 64 + c0;
#pragma unroll
                for (int nf = 0; nf < 8; nf++) {
                    float2 bb = *reinterpret_cast<const float2*>(bsl + wn * 64 + c0 + nf * 8);
                    float2 v = make_float2(acc[mf][nf][half * 2] + bb.x,
                                           acc[mf][nf][half * 2 + 1] + bb.y);
                    *reinterpret_cast<float2*>(dst + nf * 8) = v;
                }
            }
        }
    }
}

// ---------------------------------------------------------------------------
// Counting sort by target
// ---------------------------------------------------------------------------
__global__ __launch_bounds__(256) void zero_cnt_kernel() {
    int i = blockIdx.x * blockDim.x + threadIdx.x;
    if (i < NT) g_cnt[i] = 0;
}

__global__ __launch_bounds__(256) void hist_kernel(const int* __restrict__ EI) {
    int i = blockIdx.x * blockDim.x + threadIdx.x;
    if (i >= TOT_E) return;
    int r = i / N_EDGES;
    int e = i - r * N_EDGES;
    int tgt = EI[(size_t)r * 2 * N_EDGES + N_EDGES + e];
    atomicAdd(&g_cnt[tgt], 1);
}

__global__ __launch_bounds__(256) void scan_part_kernel() {
    __shared__ int s[256];
    int b = blockIdx.x, t = threadIdx.x;
    int base = b * 1024 + t * 4;
    int v = 0;
#pragma unroll
    for (int j = 0; j < 4; j++) {
        int idx = base + j;
        if (idx < NT) v += g_cnt[idx];
    }
    s[t] = v;
    __syncthreads();
    for (int off = 128; off > 0; off >>= 1) {
        if (t < off) s[t] += s[t + off];
        __syncthreads();
    }
    if (t == 0) g_part[b] = s[0];
}

__global__ __launch_bounds__(128) void scan_top_kernel() {
    __shared__ int s[128];
    int t = threadIdx.x;
    int v = (t < NBLK1K) ? g_part[t] : 0;
    s[t] = v;
    __syncthreads();
    for (int d = 1; d < 128; d <<= 1) {
        int add = (t >= d) ? s[t - d] : 0;
        __syncthreads();
        s[t] += add;
        __syncthreads();
    }
    if (t < NBLK1K) g_partoff[t] = s[t] - v;
    if (t == NBLK1K - 1) g_off[NT] = s[t];
}

__global__ __launch_bounds__(256) void scan_final_kernel() {
    __shared__ int s[256];
    int b = blockIdx.x, t = threadIdx.x;
    int base = b * 1024 + t * 4;
    int e[4], local[4];
    int sum = 0;
#pragma unroll
    for (int j = 0; j < 4; j++) {
        int idx = base + j;
        e[j] = (idx < NT) ? g_cnt[idx] : 0;
        local[j] = sum;
        sum += e[j];
    }
    s[t] = sum;
    __syncthreads();
    int own = sum;
    for (int d = 1; d < 256; d <<= 1) {
        int add = (t >= d) ? s[t - d] : 0;
        __syncthreads();
        s[t] += add;
        __syncthreads();
    }
    int texcl = s[t] - own;
    int baseoff = g_partoff[b] + texcl;
#pragma unroll
    for (int j = 0; j < 4; j++) {
        int idx = base + j;
        if (idx < NT) {
            int o = baseoff + local[j];
            g_off[idx] = o;
            g_cursor[idx] = o;
        }
    }
}

__global__ __launch_bounds__(256) void reorder_kernel(const int* __restrict__ EI) {
    int i = blockIdx.x * blockDim.x + threadIdx.x;
    if (i >= TOT_E) return;
    int r = i / N_EDGES;
    int e = i - r * N_EDGES;
    const int* base = EI + (size_t)r * 2 * N_EDGES;
    int src = base[e];
    int tgt = base[N_EDGES + e];
    int pos = atomicAdd(&g_cursor[tgt], 1);
    g_payload[pos] = (r << 17) | src;
}

// ---------------------------------------------------------------------------
// Gather: one warp per target; out[t] += sum_e T[src_e, r_e] + cnt_r * b_r
// ---------------------------------------------------------------------------
__global__ __launch_bounds__(256) void gather_kernel(const float* __restrict__ b,
                                                     float* __restrict__ out) {
    const int lane = threadIdx.x & 31;
    const int wid = threadIdx.x >> 5;
    const int t = blockIdx.x * 8 + wid;
    if (t >= N_NODES) return;

    const int beg = g_off[t];
    const int end = g_off[t + 1];
    if (beg == end) return;

    float4 acc = make_float4(0.f, 0.f, 0.f, 0.f);
    int c0 = 0, c1 = 0, c2 = 0, c3 = 0;

    for (int base = beg; base < end; base += 32) {
        int i = base + lane;
        int p = (i < end) ? g_payload[i] : 0;
        int m = min(end - base, 32);
        for (int j = 0; j < m; j++) {
            int pj = __shfl_sync(0xffffffffu, p, j);
            int r = pj >> 17;
            int src = pj & 131071;
            float4 v = reinterpret_cast<const float4*>(
                g_T + (size_t)src * 512 + (size_t)r * 128)[lane];
            acc.x += v.x; acc.y += v.y; acc.z += v.z; acc.w += v.w;
            c0 += (r == 0); c1 += (r == 1); c2 += (r == 2); c3 += (r == 3);
        }
    }

    float cf[4] = {(float)c0, (float)c1, (float)c2, (float)c3};
#pragma unroll
    for (int r = 0; r < 4; r++) {
        float4 br = reinterpret_cast<const float4*>(b + (size_t)r * 128)[lane];
        acc.x += cf[r] * br.x; acc.y += cf[r] * br.y;
        acc.z += cf[r] * br.z; acc.w += cf[r] * br.w;
    }

    float4* orow = reinterpret_cast<float4*>(out + (size_t)t * 128);
    float4 o = orow[lane];
    o.x += acc.x; o.y += acc.y; o.z += acc.z; o.w += acc.w;
    orow[lane] = o;
}

// ---------------------------------------------------------------------------
extern "C" void kernel_launch(void* const* d_in, const int* in_sizes, int n_in,
                              void* d_out, int out_size) {
    const float* x   = (const float*)d_in[0];   // [100000,128]
    const int*   ei  = (const int*)  d_in[1];   // [4,2,500000]
    const float* W   = (const float*)d_in[2];   // [4,128,128]
    const float* b   = (const float*)d_in[3];   // [4,128]
    const float* Wsl = (const float*)d_in[4];   // [128,128]
    const float* bsl = (const float*)d_in[5];   // [128]
    float* out = (float*)d_out;                 // [100000,128]

    // One-time host objects (created on the first, non-capture, correctness call).
    // No device memory involved; graph nodes per call are identical.
    static cudaStream_t s2 = nullptr;
    static cudaEvent_t ev_fork = nullptr, ev_join = nullptr;
    static bool overlap_ok = false;
    if (!s2) {
        overlap_ok =
            (cudaStreamCreateWithFlags(&s2, cudaStreamNonBlocking) == cudaSuccess) &&
            (cudaEventCreateWithFlags(&ev_fork, cudaEventDisableTiming) == cudaSuccess) &&
            (cudaEventCreateWithFlags(&ev_join, cudaEventDisableTiming) == cudaSuccess);
    }

    cudaStream_t sortStream = overlap_ok ? s2 : (cudaStream_t)0;
    if (overlap_ok) {
        cudaEventRecord(ev_fork, 0);
        cudaStreamWaitEvent(s2, ev_fork, 0);
    }

    // Branch A (default stream): conv + tensor-core transform (writes g_T, out selfloop)
    conv_x_kernel<<<(N_NODES * 32 + 255) / 256, 256>>>(x);
    conv_w_kernel<<<(640 * 32 + 255) / 256, 256>>>(W, Wsl);
    dim3 grid(782, 5);
    gemm_mma_kernel<<<grid, 256>>>(bsl, out);

    // Branch B (side stream): counting sort of edges by target
    zero_cnt_kernel<<<(NT + 255) / 256, 256, 0, sortStream>>>();
    hist_kernel<<<(TOT_E + 255) / 256, 256, 0, sortStream>>>(ei);
    scan_part_kernel<<<NBLK1K, 256, 0, sortStream>>>();
    scan_top_kernel<<<1, 128, 0, sortStream>>>();
    scan_final_kernel<<<NBLK1K, 256, 0, sortStream>>>();
    reorder_kernel<<<(TOT_E + 255) / 256, 256, 0, sortStream>>>(ei);

    if (overlap_ok) {
        cudaEventRecord(ev_join, s2);
        cudaStreamWaitEvent(0, ev_join, 0);
    }

    // Join: atomic-free per-target gather + bias + self-loop RMW
    gather_kernel<<<(N_NODES + 7) / 8, 256>>>(b, out);
}

// round 7
// speedup vs baseline: 2.6724x; 1.3931x over previous
#include <cuda_runtime.h>
#include <cuda_fp16.h>
#include <cstdint>

// Problem constants
#define N_NODES 100000
#define N_PAD   100096          // 782 * 128
#define NT      100096          // padded bin count for sort
#define NBLK1K  98              // ceil(NT/1024)
#define D 128
#define N_REL 4
#define N_EDGES 500000
#define TOT_E   (N_REL * N_EDGES)   // 2,000,000

// Device scratch (globals; no runtime allocation allowed)
__device__ __half g_T[(size_t)N_NODES * 512];       // per-node transformed rows (fp16)
__device__ __half g_Xs[(size_t)N_PAD * 128];        // xh per node (fp16)
__device__ __half g_Bs[(size_t)640 * 128];          // Wh rows: 0..511 W, 512..639 Wsl
__device__ int g_cnt[NT];
__device__ int g_off[NT + 1];
__device__ int g_cursor[NT];
__device__ int g_part[NBLK1K];
__device__ int g_partoff[NBLK1K];
__device__ int g_payload[TOT_E];

// ---------------------------------------------------------------------------
// helpers
// ---------------------------------------------------------------------------
__device__ __forceinline__ uint32_t smem_u32(const void* p) {
    uint32_t a;
    asm("{ .reg .u64 t; cvta.to.shared.u64 t, %1; cvt.u32.u64 %0, t; }" : "=r"(a) : "l"(p));
    return a;
}
__device__ __forceinline__ void ldsm_x4(uint32_t addr, uint32_t& r0, uint32_t& r1,
                                        uint32_t& r2, uint32_t& r3) {
    asm volatile("ldmatrix.sync.aligned.m8n8.x4.shared.b16 {%0,%1,%2,%3}, [%4];"
                 : "=r"(r0), "=r"(r1), "=r"(r2), "=r"(r3) : "r"(addr));
}
__device__ __forceinline__ void mma16816(float* c, uint32_t a0, uint32_t a1, uint32_t a2,
                                         uint32_t a3, uint32_t b0, uint32_t b1) {
    asm volatile("mma.sync.aligned.m16n8k16.row.col.f32.f16.f16.f32 "
                 "{%0,%1,%2,%3}, {%4,%5,%6,%7}, {%8,%9}, {%0,%1,%2,%3};"
                 : "+f"(c[0]), "+f"(c[1]), "+f"(c[2]), "+f"(c[3])
                 : "r"(a0), "r"(a1), "r"(a2), "r"(a3), "r"(b0), "r"(b1));
}

// ---------------------------------------------------------------------------
// Conversion kernels: fp32 -> fp16
// ---------------------------------------------------------------------------
__global__ __launch_bounds__(256) void conv_x_kernel(const float* __restrict__ x) {
    size_t i = (size_t)blockIdx.x * blockDim.x + threadIdx.x;
    if (i >= (size_t)N_NODES * 32) return;
    size_t row = i >> 5;
    int c4 = (int)(i & 31);
    float4 v = reinterpret_cast<const float4*>(x)[i];
    __half h[4];
    h[0] = __float2half_rn(v.x); h[1] = __float2half_rn(v.y);
    h[2] = __float2half_rn(v.z); h[3] = __float2half_rn(v.w);
    *reinterpret_cast<uint2*>(&g_Xs[row * 128 + c4 * 4]) = *reinterpret_cast<uint2*>(h);
}

__global__ __launch_bounds__(256) void conv_w_kernel(const float* __restrict__ W,
                                                     const float* __restrict__ Wsl) {
    int i = blockIdx.x * blockDim.x + threadIdx.x;
    if (i >= 640 * 32) return;
    int row = i >> 5;
    int c4 = i & 31;
    const float* src = (row < 512) ? (W + (size_t)row * 128) : (Wsl + (size_t)(row - 512) * 128);
    float4 v = reinterpret_cast<const float4*>(src)[c4];
    __half h[4];
    h[0] = __float2half_rn(v.x); h[1] = __float2half_rn(v.y);
    h[2] = __float2half_rn(v.z); h[3] = __float2half_rn(v.w);
    *reinterpret_cast<uint2*>(&g_Bs[(size_t)row * 128 + c4 * 4]) = *reinterpret_cast<uint2*>(h);
}

// ---------------------------------------------------------------------------
// mma.sync GEMM: C[100096 x 640] = xh @ Wh^T   (fp16, K=128 in 2 steps of 64)
//   grid = (782, 5); CTA tile M=128, N=128; 8 warps 4(M)x2(N), warp 32x64.
//   nt<4 -> g_T (fp16) ; nt==4 -> out (fp32, +bsl)
// ---------------------------------------------------------------------------
__global__ __launch_bounds__(256, 2) void gemm_mma_kernel(const float* __restrict__ bsl,
                                                          float* __restrict__ out) {
    __shared__ __half sA[128 * 64];
    __shared__ __half sB[128 * 64];

    const int tid = threadIdx.x;
    const int lane = tid & 31;
    const int wid = tid >> 5;
    const int wm = wid & 3;
    const int wn = wid >> 2;
    const int mt = blockIdx.x;
    const int nt = blockIdx.y;
    const int m0 = mt * 128;

    float acc[2][8][4];
#pragma unroll
    for (int i = 0; i < 2; i++)
#pragma unroll
        for (int j = 0; j < 8; j++)
#pragma unroll
            for (int k = 0; k < 4; k++) acc[i][j][k] = 0.0f;

    const __half* Abase = g_Xs + (size_t)m0 * 128;
    const __half* Bbase = g_Bs + (size_t)nt * 128 * 128;
    const uint32_t sAu = smem_u32(sA);
    const uint32_t sBu = smem_u32(sB);

#pragma unroll 1
    for (int step = 0; step < 2; step++) {
        const int kc = step * 64;
#pragma unroll
        for (int it = 0; it < 4; it++) {
            int idx = tid + it * 256;
            int row = idx >> 3;
            int ch = idx & 7;
            int sw = (ch ^ (row & 7)) << 4;
            float4 va = *reinterpret_cast<const float4*>(Abase + (size_t)row * 128 + kc + ch * 8);
            *reinterpret_cast<float4*>(reinterpret_cast<char*>(sA) + row * 128 + sw) = va;
            float4 vb = *reinterpret_cast<const float4*>(Bbase + (size_t)row * 128 + kc + ch * 8);
            *reinterpret_cast<float4*>(reinterpret_cast<char*>(sB) + row * 128 + sw) = vb;
        }
        __syncthreads();

#pragma unroll
        for (int kq = 0; kq < 4; kq++) {
            uint32_t a[2][4];
#pragma unroll
            for (int mf = 0; mf < 2; mf++) {
                int row = wm * 32 + mf * 16 + (lane & 15);
                int kch = kq * 2 + (lane >> 4);
                uint32_t addr = sAu + row * 128 + ((kch ^ (row & 7)) << 4);
                ldsm_x4(addr, a[mf][0], a[mf][1], a[mf][2], a[mf][3]);
            }
            uint32_t b[8][2];
#pragma unroll
            for (int np = 0; np < 4; np++) {
                int n = wn * 64 + np * 16 + ((lane >> 4) << 3) + (lane & 7);
                int kch = kq * 2 + ((lane >> 3) & 1);
                uint32_t addr = sBu + n * 128 + ((kch ^ (n & 7)) << 4);
                ldsm_x4(addr, b[np * 2][0], b[np * 2][1], b[np * 2 + 1][0], b[np * 2 + 1][1]);
            }
#pragma unroll
            for (int mf = 0; mf < 2; mf++)
#pragma unroll
                for (int nf = 0; nf < 8; nf++)
                    mma16816(acc[mf][nf], a[mf][0], a[mf][1], a[mf][2], a[mf][3],
                             b[nf][0], b[nf][1]);
        }
        __syncthreads();
    }

    const int r0 = lane >> 2;
    const int c0 = (lane & 3) * 2;
    if (nt < N_REL) {
#pragma unroll
        for (int mf = 0; mf < 2; mf++) {
#pragma unroll
            for (int half = 0; half < 2; half++) {
                int gm = m0 + wm * 32 + mf * 16 + r0 + half * 8;
                if (gm >= N_NODES) continue;
                __half* dst = g_T + (size_t)gm * 512 + nt * 128 + wn * 64 + c0;
#pragma unroll
                for (int nf = 0; nf < 8; nf++) {
                    __half2 h = __floats2half2_rn(acc[mf][nf][half * 2],
                                                  acc[mf][nf][half * 2 + 1]);
                    *reinterpret_cast<__half2*>(dst + nf * 8) = h;
                }
            }
        }
    } else {
#pragma unroll
        for (int mf = 0; mf < 2; mf++) {
#pragma unroll
            for (int half = 0; half < 2; half++) {
                int gm = m0 + wm * 32 + mf * 16 + r0 + half * 8;
                if (gm >= N_NODES) continue;
                float* dst = out + (size_t)gm * 128 + wn * 64 + c0;
#pragma unroll
                for (int nf = 0; nf < 8; nf++) {
                    float2 bb = *reinterpret_cast<const float2*>(bsl + wn * 64 + c0 + nf * 8);
                    float2 v = make_float2(acc[mf][nf][half * 2] + bb.x,
                                           acc[mf][nf][half * 2 + 1] + bb.y);
                    *reinterpret_cast<float2*>(dst + nf * 8) = v;
                }
            }
        }
    }
}

// ---------------------------------------------------------------------------
// Counting sort by target
// ---------------------------------------------------------------------------
__global__ __launch_bounds__(256) void zero_cnt_kernel() {
    int i = blockIdx.x * blockDim.x + threadIdx.x;
    if (i < NT) g_cnt[i] = 0;
}

__global__ __launch_bounds__(256) void hist_kernel(const int* __restrict__ EI) {
    int i = blockIdx.x * blockDim.x + threadIdx.x;
    if (i >= TOT_E) return;
    int r = i / N_EDGES;
    int e = i - r * N_EDGES;
    int tgt = EI[(size_t)r * 2 * N_EDGES + N_EDGES + e];
    atomicAdd(&g_cnt[tgt], 1);
}

__global__ __launch_bounds__(256) void scan_part_kernel() {
    __shared__ int s[256];
    int b = blockIdx.x, t = threadIdx.x;
    int base = b * 1024 + t * 4;
    int v = 0;
#pragma unroll
    for (int j = 0; j < 4; j++) {
        int idx = base + j;
        if (idx < NT) v += g_cnt[idx];
    }
    s[t] = v;
    __syncthreads();
    for (int off = 128; off > 0; off >>= 1) {
        if (t < off) s[t] += s[t + off];
        __syncthreads();
    }
    if (t == 0) g_part[b] = s[0];
}

__global__ __launch_bounds__(128) void scan_top_kernel() {
    __shared__ int s[128];
    int t = threadIdx.x;
    int v = (t < NBLK1K) ? g_part[t] : 0;
    s[t] = v;
    __syncthreads();
    for (int d = 1; d < 128; d <<= 1) {
        int add = (t >= d) ? s[t - d] : 0;
        __syncthreads();
        s[t] += add;
        __syncthreads();
    }
    if (t < NBLK1K) g_partoff[t] = s[t] - v;
    if (t == NBLK1K - 1) g_off[NT] = s[t];
}

__global__ __launch_bounds__(256) void scan_final_kernel() {
    __shared__ int s[256];
    int b = blockIdx.x, t = threadIdx.x;
    int base = b * 1024 + t * 4;
    int e[4], local[4];
    int sum = 0;
#pragma unroll
    for (int j = 0; j < 4; j++) {
        int idx = base + j;
        e[j] = (idx < NT) ? g_cnt[idx] : 0;
        local[j] = sum;
        sum += e[j];
    }
    s[t] = sum;
    __syncthreads();
    int own = sum;
    for (int d = 1; d < 256; d <<= 1) {
        int add = (t >= d) ? s[t - d] : 0;
        __syncthreads();
        s[t] += add;
        __syncthreads();
    }
    int texcl = s[t] - own;
    int baseoff = g_partoff[b] + texcl;
#pragma unroll
    for (int j = 0; j < 4; j++) {
        int idx = base + j;
        if (idx < NT) {
            int o = baseoff + local[j];
            g_off[idx] = o;
            g_cursor[idx] = o;
        }
    }
}

__global__ __launch_bounds__(256) void reorder_kernel(const int* __restrict__ EI) {
    int i = blockIdx.x * blockDim.x + threadIdx.x;
    if (i >= TOT_E) return;
    int r = i / N_EDGES;
    int e = i - r * N_EDGES;
    const int* base = EI + (size_t)r * 2 * N_EDGES;
    int src = base[e];
    int tgt = base[N_EDGES + e];
    int pos = atomicAdd(&g_cursor[tgt], 1);
    g_payload[pos] = (r << 17) | src;
}

// ---------------------------------------------------------------------------
// Gather (fp16 rows): one warp per target, two edges per step (half-warp each).
// Lane = group(1b)*16 + sub(4b); lane loads uint4 = 8 halves of its edge's row.
// Shuffle is executed by ALL lanes (clamped index); only load/accum predicated.
// ---------------------------------------------------------------------------
__global__ __launch_bounds__(256) void gather_kernel(const float* __restrict__ b,
                                                     float* __restrict__ out) {
    const int lane = threadIdx.x & 31;
    const int wid = threadIdx.x >> 5;
    const int t = blockIdx.x * 8 + wid;
    if (t >= N_NODES) return;

    const int beg = g_off[t];
    const int end = g_off[t + 1];
    if (beg == end) return;

    const int group = lane >> 4;     // 0 or 1
    const int sub = lane & 15;       // feature chunk: halves sub*8 .. sub*8+7

    float acc[8];
#pragma unroll
    for (int i = 0; i < 8; i++) acc[i] = 0.0f;
    int c0 = 0, c1 = 0, c2 = 0, c3 = 0;

    for (int base = beg; base < end; base += 32) {
        int i = base + lane;
        int p = (i < end) ? g_payload[i] : 0;
        int m = min(end - base, 32);
        for (int j = 0; j < m; j += 2) {
            int jj = j + group;
            // All 32 lanes execute the shuffle (index clamped); predicate only the use.
            int pj = __shfl_sync(0xffffffffu, p, min(jj, m - 1));
            if (jj < m) {
                int r = pj >> 17;
                int src = pj & 131071;
                uint4 raw = reinterpret_cast<const uint4*>(
                    g_T + (size_t)src * 512 + (size_t)r * 128 + sub * 8)[0];
                const __half2* h2 = reinterpret_cast<const __half2*>(&raw);
#pragma unroll
                for (int q = 0; q < 4; q++) {
                    float2 f = __half22float2(h2[q]);
                    acc[q * 2 + 0] += f.x;
                    acc[q * 2 + 1] += f.y;
                }
                c0 += (r == 0); c1 += (r == 1); c2 += (r == 2); c3 += (r == 3);
            }
        }
    }

    // combine the two half-warps (same feature chunk in both groups)
#pragma unroll
    for (int i = 0; i < 8; i++) acc[i] += __shfl_xor_sync(0xffffffffu, acc[i], 16);
    c0 += __shfl_xor_sync(0xffffffffu, c0, 16);
    c1 += __shfl_xor_sync(0xffffffffu, c1, 16);
    c2 += __shfl_xor_sync(0xffffffffu, c2, 16);
    c3 += __shfl_xor_sync(0xffffffffu, c3, 16);

    if (group == 0) {
        float cf[4] = {(float)c0, (float)c1, (float)c2, (float)c3};
#pragma unroll
        for (int r = 0; r < 4; r++) {
            const float* br = b + (size_t)r * 128 + sub * 8;
#pragma unroll
            for (int q = 0; q < 8; q++) acc[q] += cf[r] * br[q];
        }
        float* dst = out + (size_t)t * 128 + sub * 8;
        float4 o0 = reinterpret_cast<float4*>(dst)[0];
        float4 o1 = reinterpret_cast<float4*>(dst)[1];
        o0.x += acc[0]; o0.y += acc[1]; o0.z += acc[2]; o0.w += acc[3];
        o1.x += acc[4]; o1.y += acc[5]; o1.z += acc[6]; o1.w += acc[7];
        reinterpret_cast<float4*>(dst)[0] = o0;
        reinterpret_cast<float4*>(dst)[1] = o1;
    }
}

// ---------------------------------------------------------------------------
extern "C" void kernel_launch(void* const* d_in, const int* in_sizes, int n_in,
                              void* d_out, int out_size) {
    const float* x   = (const float*)d_in[0];   // [100000,128]
    const int*   ei  = (const int*)  d_in[1];   // [4,2,500000]
    const float* W   = (const float*)d_in[2];   // [4,128,128]
    const float* b   = (const float*)d_in[3];   // [4,128]
    const float* Wsl = (const float*)d_in[4];   // [128,128]
    const float* bsl = (const float*)d_in[5];   // [128]
    float* out = (float*)d_out;                 // [100000,128]

    // One-time host objects (no device memory involved)
    static cudaStream_t s2 = nullptr;
    static cudaEvent_t ev_fork = nullptr, ev_join = nullptr;
    static bool overlap_ok = false;
    if (!s2) {
        overlap_ok =
            (cudaStreamCreateWithFlags(&s2, cudaStreamNonBlocking) == cudaSuccess) &&
            (cudaEventCreateWithFlags(&ev_fork, cudaEventDisableTiming) == cudaSuccess) &&
            (cudaEventCreateWithFlags(&ev_join, cudaEventDisableTiming) == cudaSuccess);
    }

    cudaStream_t sortStream = overlap_ok ? s2 : (cudaStream_t)0;
    if (overlap_ok) {
        cudaEventRecord(ev_fork, 0);
        cudaStreamWaitEvent(s2, ev_fork, 0);
    }

    // Branch A (default stream): conv + tensor-core transform (writes g_T, out selfloop)
    conv_x_kernel<<<(N_NODES * 32 + 255) / 256, 256>>>(x);
    conv_w_kernel<<<(640 * 32 + 255) / 256, 256>>>(W, Wsl);
    dim3 grid(782, 5);
    gemm_mma_kernel<<<grid, 256>>>(bsl, out);

    // Branch B (side stream): counting sort of edges by target
    zero_cnt_kernel<<<(NT + 255) / 256, 256, 0, sortStream>>>();
    hist_kernel<<<(TOT_E + 255) / 256, 256, 0, sortStream>>>(ei);
    scan_part_kernel<<<NBLK1K, 256, 0, sortStream>>>();
    scan_top_kernel<<<1, 128, 0, sortStream>>>();
    scan_final_kernel<<<NBLK1K, 256, 0, sortStream>>>();
    reorder_kernel<<<(TOT_E + 255) / 256, 256, 0, sortStream>>>(ei);

    if (overlap_ok) {
        cudaEventRecord(ev_join, s2);
        cudaStreamWaitEvent(0, ev_join, 0);
    }

    // Join: atomic-free per-target gather + bias + self-loop RMW
    gather_kernel<<<(N_NODES + 7) / 8, 256>>>(b, out);
}

// round 8
// speedup vs baseline: 2.9817x; 1.1157x over previous
#include <cuda_runtime.h>
#include <cuda_fp16.h>
#include <cstdint>

// Problem constants
#define N_NODES 100000
#define N_PAD   100096          // 782 * 128
#define NT2     400384          // 4*N_NODES padded to 391*1024
#define NBLK2   391             // NT2 / 1024
#define D 128
#define N_REL 4
#define N_EDGES 500000
#define TOT_E   (N_REL * N_EDGES)   // 2,000,000
#define KROW    640             // S row: [S0|S1|S2|S3|x] halves

// Device scratch (globals; zero-initialized at load; no runtime allocation)
__device__ __half g_Xs[(size_t)N_NODES * 128];       // x rows fp16 (gather source, 25.6MB)
__device__ __half g_S[(size_t)N_PAD * KROW];         // aggregated features per node (128MB)
__device__ __half g_Wx[(size_t)128 * KROW];          // [W0|W1|W2|W3|Wsl] per out-feature row
__device__ float g_C4[(size_t)N_NODES * 4];          // per-(node,rel) edge counts
__device__ int g_cnt[NT2];
__device__ int g_off[NT2 + 1];
__device__ int g_cursor[NT2];
__device__ int g_part[NBLK2];
__device__ int g_partoff[NBLK2];
__device__ int g_payload[TOT_E];                     // src node per sorted edge

// ---------------------------------------------------------------------------
// helpers
// ---------------------------------------------------------------------------
__device__ __forceinline__ uint32_t smem_u32(const void* p) {
    uint32_t a;
    asm("{ .reg .u64 t; cvta.to.shared.u64 t, %1; cvt.u32.u64 %0, t; }" : "=r"(a) : "l"(p));
    return a;
}
__device__ __forceinline__ void ldsm_x4(uint32_t addr, uint32_t& r0, uint32_t& r1,
                                        uint32_t& r2, uint32_t& r3) {
    asm volatile("ldmatrix.sync.aligned.m8n8.x4.shared.b16 {%0,%1,%2,%3}, [%4];"
                 : "=r"(r0), "=r"(r1), "=r"(r2), "=r"(r3) : "r"(addr));
}
__device__ __forceinline__ void mma16816(float* c, uint32_t a0, uint32_t a1, uint32_t a2,
                                         uint32_t a3, uint32_t b0, uint32_t b1) {
    asm volatile("mma.sync.aligned.m16n8k16.row.col.f32.f16.f16.f32 "
                 "{%0,%1,%2,%3}, {%4,%5,%6,%7}, {%8,%9}, {%0,%1,%2,%3};"
                 : "+f"(c[0]), "+f"(c[1]), "+f"(c[2]), "+f"(c[3])
                 : "r"(a0), "r"(a1), "r"(a2), "r"(a3), "r"(b0), "r"(b1));
}

// ---------------------------------------------------------------------------
// conv_x: fp32 x -> fp16 g_Xs rows AND xh section of g_S (cols 512..639)
// ---------------------------------------------------------------------------
__global__ __launch_bounds__(256) void conv_x_kernel(const float* __restrict__ x) {
    size_t i = (size_t)blockIdx.x * blockDim.x + threadIdx.x;
    if (i >= (size_t)N_NODES * 32) return;
    size_t row = i >> 5;
    int c4 = (int)(i & 31);
    float4 v = reinterpret_cast<const float4*>(x)[i];
    __half h[4];
    h[0] = __float2half_rn(v.x); h[1] = __float2half_rn(v.y);
    h[2] = __float2half_rn(v.z); h[3] = __float2half_rn(v.w);
    uint2 hv = *reinterpret_cast<uint2*>(h);
    *reinterpret_cast<uint2*>(&g_Xs[row * 128 + c4 * 4]) = hv;
    *reinterpret_cast<uint2*>(&g_S[row * KROW + 512 + c4 * 4]) = hv;
}

// ---------------------------------------------------------------------------
// conv_w: build g_Wx[f][0..639] = [W0[f]|W1[f]|W2[f]|W3[f]|Wsl[f]] fp16
// ---------------------------------------------------------------------------
__global__ __launch_bounds__(256) void conv_w_kernel(const float* __restrict__ W,
                                                     const float* __restrict__ Wsl) {
    int i = blockIdx.x * blockDim.x + threadIdx.x;  // one float4 per thread; 128*160
    if (i >= 128 * 160) return;
    int f = i / 160;
    int c4 = i - f * 160;      // float4 index within 640 cols
    int c = c4 * 4;
    float4 v;
    if (c < 512) {
        int r = c >> 7, dd = c & 127;
        v = *reinterpret_cast<const float4*>(W + (size_t)r * 16384 + (size_t)f * 128 + dd);
    } else {
        v = *reinterpret_cast<const float4*>(Wsl + (size_t)f * 128 + (c - 512));
    }
    __half h[4];
    h[0] = __float2half_rn(v.x); h[1] = __float2half_rn(v.y);
    h[2] = __float2half_rn(v.z); h[3] = __float2half_rn(v.w);
    *reinterpret_cast<uint2*>(&g_Wx[(size_t)f * KROW + c]) = *reinterpret_cast<uint2*>(h);
}

// ---------------------------------------------------------------------------
// Counting sort by key = tgt*4 + rel
// ---------------------------------------------------------------------------
__global__ __launch_bounds__(256) void zero_cnt_kernel() {
    int i = blockIdx.x * blockDim.x + threadIdx.x;
    if (i < NT2) g_cnt[i] = 0;
}

__global__ __launch_bounds__(256) void hist_kernel(const int* __restrict__ EI) {
    int i = blockIdx.x * blockDim.x + threadIdx.x;
    if (i >= TOT_E) return;
    int r = i / N_EDGES;
    int e = i - r * N_EDGES;
    int tgt = EI[(size_t)r * 2 * N_EDGES + N_EDGES + e];
    atomicAdd(&g_cnt[tgt * 4 + r], 1);
}

__global__ __launch_bounds__(256) void scan_part_kernel() {
    __shared__ int s[256];
    int b = blockIdx.x, t = threadIdx.x;
    int base = b * 1024 + t * 4;
    int v = 0;
#pragma unroll
    for (int j = 0; j < 4; j++) v += g_cnt[base + j];   // NT2 is exact multiple of 1024
    s[t] = v;
    __syncthreads();
    for (int off = 128; off > 0; off >>= 1) {
        if (t < off) s[t] += s[t + off];
        __syncthreads();
    }
    if (t == 0) g_part[b] = s[0];
}

__global__ __launch_bounds__(512) void scan_top_kernel() {
    __shared__ int s[512];
    int t = threadIdx.x;
    int v = (t < NBLK2) ? g_part[t] : 0;
    s[t] = v;
    __syncthreads();
    for (int d = 1; d < 512; d <<= 1) {
        int add = (t >= d) ? s[t - d] : 0;
        __syncthreads();
        s[t] += add;
        __syncthreads();
    }
    if (t < NBLK2) g_partoff[t] = s[t] - v;
    if (t == NBLK2 - 1) g_off[NT2] = s[t];
}

__global__ __launch_bounds__(256) void scan_final_kernel() {
    __shared__ int s[256];
    int b = blockIdx.x, t = threadIdx.x;
    int base = b * 1024 + t * 4;
    int e[4], local[4];
    int sum = 0;
#pragma unroll
    for (int j = 0; j < 4; j++) {
        e[j] = g_cnt[base + j];
        local[j] = sum;
        sum += e[j];
    }
    s[t] = sum;
    __syncthreads();
    int own = sum;
    for (int d = 1; d < 256; d <<= 1) {
        int add = (t >= d) ? s[t - d] : 0;
        __syncthreads();
        s[t] += add;
        __syncthreads();
    }
    int texcl = s[t] - own;
    int baseoff = g_partoff[b] + texcl;
#pragma unroll
    for (int j = 0; j < 4; j++) {
        int o = baseoff + local[j];
        g_off[base + j] = o;
        g_cursor[base + j] = o;
    }
}

__global__ __launch_bounds__(256) void reorder_kernel(const int* __restrict__ EI) {
    int i = blockIdx.x * blockDim.x + threadIdx.x;
    if (i >= TOT_E) return;
    int r = i / N_EDGES;
    int e = i - r * N_EDGES;
    const int* base = EI + (size_t)r * 2 * N_EDGES;
    int src = base[e];
    int tgt = base[N_EDGES + e];
    int pos = atomicAdd(&g_cursor[tgt * 4 + r], 1);
    g_payload[pos] = src;
}

// ---------------------------------------------------------------------------
// Gather: one warp per target t. For each rel r: sum fp16 x rows of in-edges
// into fp32 acc, store fp16 into S[t][r*128..], count -> g_C4.
// Half-warp per edge (16 lanes x 16B = 256B row), two edges per step.
// ---------------------------------------------------------------------------
__global__ __launch_bounds__(256) void gather_kernel() {
    const int lane = threadIdx.x & 31;
    const int wid = threadIdx.x >> 5;
    const int t = blockIdx.x * 8 + wid;
    if (t >= N_NODES) return;

    const int group = lane >> 4;     // 0 or 1
    const int sub = lane & 15;       // halves sub*8 .. sub*8+7

    int o[5];
#pragma unroll
    for (int j = 0; j < 5; j++) o[j] = g_off[t * 4 + j];

#pragma unroll 1
    for (int r = 0; r < 4; r++) {
        const int beg = o[r];
        const int end = o[r + 1];

        float acc[8];
#pragma unroll
        for (int i = 0; i < 8; i++) acc[i] = 0.0f;

        for (int base = beg; base < end; base += 32) {
            int i = base + lane;
            int p = (i < end) ? g_payload[i] : 0;
            int m = min(end - base, 32);
            for (int j = 0; j < m; j += 2) {
                int jj = j + group;
                int src = __shfl_sync(0xffffffffu, p, min(jj, m - 1));
                if (jj < m) {
                    uint4 raw = *reinterpret_cast<const uint4*>(
                        g_Xs + (size_t)src * 128 + sub * 8);
                    const __half2* h2 = reinterpret_cast<const __half2*>(&raw);
#pragma unroll
                    for (int q = 0; q < 4; q++) {
                        float2 f = __half22float2(h2[q]);
                        acc[q * 2 + 0] += f.x;
                        acc[q * 2 + 1] += f.y;
                    }
                }
            }
        }
        // combine the two half-warps (same feature chunk in both groups)
#pragma unroll
        for (int i = 0; i < 8; i++) acc[i] += __shfl_xor_sync(0xffffffffu, acc[i], 16);

        if (group == 0) {
            __half h[8];
#pragma unroll
            for (int q = 0; q < 8; q++) h[q] = __float2half_rn(acc[q]);
            *reinterpret_cast<uint4*>(&g_S[(size_t)t * KROW + r * 128 + sub * 8]) =
                *reinterpret_cast<uint4*>(h);
        }
        if (lane == 0) g_C4[(size_t)t * 4 + r] = (float)(end - beg);
    }
}

// ---------------------------------------------------------------------------
// GEMM: out[100096 x 128] = S[.,640] @ Wx^T + Sum_r C4[t][r]*b[r] + bsl
//   grid = 782; CTA tile M=128, N=128; 8 warps 4(M)x2(N); K=640 in 10 steps.
// ---------------------------------------------------------------------------
__global__ __launch_bounds__(256, 2) void gemm_mma_kernel(const float* __restrict__ b,
                                                          const float* __restrict__ bsl,
                                                          float* __restrict__ out) {
    __shared__ __half sA[128 * 64];
    __shared__ __half sB[128 * 64];

    const int tid = threadIdx.x;
    const int lane = tid & 31;
    const int wid = tid >> 5;
    const int wm = wid & 3;
    const int wn = wid >> 2;
    const int m0 = blockIdx.x * 128;

    float acc[2][8][4];
#pragma unroll
    for (int i = 0; i < 2; i++)
#pragma unroll
        for (int j = 0; j < 8; j++)
#pragma unroll
            for (int k = 0; k < 4; k++) acc[i][j][k] = 0.0f;

    const __half* Abase = g_S + (size_t)m0 * KROW;
    const uint32_t sAu = smem_u32(sA);
    const uint32_t sBu = smem_u32(sB);

#pragma unroll 1
    for (int step = 0; step < 10; step++) {
        const int kc = step * 64;
#pragma unroll
        for (int it = 0; it < 4; it++) {
            int idx = tid + it * 256;
            int row = idx >> 3;
            int ch = idx & 7;
            int sw = (ch ^ (row & 7)) << 4;
            float4 va = *reinterpret_cast<const float4*>(Abase + (size_t)row * KROW + kc + ch * 8);
            *reinterpret_cast<float4*>(reinterpret_cast<char*>(sA) + row * 128 + sw) = va;
            float4 vb = *reinterpret_cast<const float4*>(g_Wx + (size_t)row * KROW + kc + ch * 8);
            *reinterpret_cast<float4*>(reinterpret_cast<char*>(sB) + row * 128 + sw) = vb;
        }
        __syncthreads();

#pragma unroll
        for (int kq = 0; kq < 4; kq++) {
            uint32_t a[2][4];
#pragma unroll
            for (int mf = 0; mf < 2; mf++) {
                int row = wm * 32 + mf * 16 + (lane & 15);
                int kch = kq * 2 + (lane >> 4);
                uint32_t addr = sAu + row * 128 + ((kch ^ (row & 7)) << 4);
                ldsm_x4(addr, a[mf][0], a[mf][1], a[mf][2], a[mf][3]);
            }
            uint32_t bb[8][2];
#pragma unroll
            for (int np = 0; np < 4; np++) {
                int n = wn * 64 + np * 16 + ((lane >> 4) << 3) + (lane & 7);
                int kch = kq * 2 + ((lane >> 3) & 1);
                uint32_t addr = sBu + n * 128 + ((kch ^ (n & 7)) << 4);
                ldsm_x4(addr, bb[np * 2][0], bb[np * 2][1], bb[np * 2 + 1][0], bb[np * 2 + 1][1]);
            }
#pragma unroll
            for (int mf = 0; mf < 2; mf++)
#pragma unroll
                for (int nf = 0; nf < 8; nf++)
                    mma16816(acc[mf][nf], a[mf][0], a[mf][1], a[mf][2], a[mf][3],
                             bb[nf][0], bb[nf][1]);
        }
        __syncthreads();
    }

    // Epilogue: + Sum_r c4[r] * b[r][col] + bsl[col]; single write of out.
    const int r0 = lane >> 2;
    const int c0 = (lane & 3) * 2;
#pragma unroll
    for (int mf = 0; mf < 2; mf++) {
#pragma unroll
        for (int half = 0; half < 2; half++) {
            int gm = m0 + wm * 32 + mf * 16 + r0 + half * 8;
            if (gm >= N_NODES) continue;
            float4 c4 = *reinterpret_cast<const float4*>(g_C4 + (size_t)gm * 4);
            float* dst = out + (size_t)gm * 128 + wn * 64 + c0;
#pragma unroll
            for (int nf = 0; nf < 8; nf++) {
                int col = wn * 64 + c0 + nf * 8;
                float2 b0 = *reinterpret_cast<const float2*>(b + 0 * 128 + col);
                float2 b1 = *reinterpret_cast<const float2*>(b + 1 * 128 + col);
                float2 b2 = *reinterpret_cast<const float2*>(b + 2 * 128 + col);
                float2 b3 = *reinterpret_cast<const float2*>(b + 3 * 128 + col);
                float2 bs = *reinterpret_cast<const float2*>(bsl + col);
                float2 v;
                v.x = acc[mf][nf][half * 2] +
                      c4.x * b0.x + c4.y * b1.x + c4.z * b2.x + c4.w * b3.x + bs.x;
                v.y = acc[mf][nf][half * 2 + 1] +
                      c4.x * b0.y + c4.y * b1.y + c4.z * b2.y + c4.w * b3.y + bs.y;
                *reinterpret_cast<float2*>(dst + nf * 8) = v;
            }
        }
    }
}

// ---------------------------------------------------------------------------
extern "C" void kernel_launch(void* const* d_in, const int* in_sizes, int n_in,
                              void* d_out, int out_size) {
    const float* x   = (const float*)d_in[0];   // [100000,128]
    const int*   ei  = (const int*)  d_in[1];   // [4,2,500000]
    const float* W   = (const float*)d_in[2];   // [4,128,128]
    const float* b   = (const float*)d_in[3];   // [4,128]
    const float* Wsl = (const float*)d_in[4];   // [128,128]
    const float* bsl = (const float*)d_in[5];   // [128]
    float* out = (float*)d_out;                 // [100000,128]

    // One-time host objects (no device memory involved)
    static cudaStream_t s2 = nullptr;
    static cudaEvent_t ev_fork = nullptr, ev_join = nullptr;
    static bool overlap_ok = false;
    if (!s2) {
        overlap_ok =
            (cudaStreamCreateWithFlags(&s2, cudaStreamNonBlocking) == cudaSuccess) &&
            (cudaEventCreateWithFlags(&ev_fork, cudaEventDisableTiming) == cudaSuccess) &&
            (cudaEventCreateWithFlags(&ev_join, cudaEventDisableTiming) == cudaSuccess);
    }

    cudaStream_t sortStream = overlap_ok ? s2 : (cudaStream_t)0;
    if (overlap_ok) {
        cudaEventRecord(ev_fork, 0);
        cudaStreamWaitEvent(s2, ev_fork, 0);
    }

    // Branch A (default stream): conversions
    conv_x_kernel<<<(N_NODES * 32 + 255) / 256, 256>>>(x);
    conv_w_kernel<<<(128 * 160 + 255) / 256, 256>>>(W, Wsl);

    // Branch B (side stream): counting sort of edges by (tgt, rel)
    zero_cnt_kernel<<<NT2 / 256, 256, 0, sortStream>>>();
    hist_kernel<<<(TOT_E + 255) / 256, 256, 0, sortStream>>>(ei);
    scan_part_kernel<<<NBLK2, 256, 0, sortStream>>>();
    scan_top_kernel<<<1, 512, 0, sortStream>>>();
    scan_final_kernel<<<NBLK2, 256, 0, sortStream>>>();
    reorder_kernel<<<(TOT_E + 255) / 256, 256, 0, sortStream>>>(ei);

    if (overlap_ok) {
        cudaEventRecord(ev_join, s2);
        cudaStreamWaitEvent(0, ev_join, 0);
    }

    // Aggregate raw features per (target, rel)
    gather_kernel<<<(N_NODES + 7) / 8, 256>>>();

    // Single fused GEMM: transform + bias + self-loop; writes out exactly once
    gemm_mma_kernel<<<782, 256>>>(b, bsl, out);
}